// round 8
// baseline (speedup 1.0000x reference)
#include <cuda_runtime.h>
#include <cuda_fp16.h>
#include <math.h>
#include <stdint.h>

// ---------------- problem constants ----------------
#define B_      32
#define HW_     56
#define L_      3136
#define C_      384
#define NH_     12
#define HD_     32
#define WS_     7
#define NTOK_   49
#define NWIN_   64
#define BN_     2048
#define MTOT_   100352
#define HID_    1536
#define QKVN_   1152
#define SHIFT_  3
#define SCALE_  0.17677669529663687f

// ---------------- scratch ----------------
__device__ __half g_win[(size_t)MTOT_ * C_];
__device__ float  g_qkv[(size_t)MTOT_ * QKVN_];
__device__ __half g_att[(size_t)MTOT_ * C_];
__device__ float  g_x1 [(size_t)MTOT_ * C_];
__device__ __half g_h2 [(size_t)MTOT_ * C_];
__device__ __half g_hid[(size_t)MTOT_ * HID_];
__device__ __half g_wh_qkv[(size_t)QKVN_ * C_];
__device__ __half g_wh_proj[(size_t)C_ * C_];
__device__ __half g_wh_fc1[(size_t)HID_ * C_];
__device__ __half g_wh_fc2[(size_t)C_ * HID_];

// ---------------- helpers ----------------
__device__ __forceinline__ void cp_async16(uint32_t saddr, const void* gptr) {
    asm volatile("cp.async.cg.shared.global [%0], [%1], 16;" :: "r"(saddr), "l"(gptr));
}
#define CP_COMMIT() asm volatile("cp.async.commit_group;" ::: "memory")
#define CP_WAIT(n)  asm volatile("cp.async.wait_group %0;" :: "n"(n) : "memory")

__device__ __forceinline__ void mma16816(float* c, const uint32_t* a, const uint32_t* b) {
    asm volatile("mma.sync.aligned.m16n8k16.row.col.f32.f16.f16.f32 "
        "{%0,%1,%2,%3}, {%4,%5,%6,%7}, {%8,%9}, {%0,%1,%2,%3};"
        : "+f"(c[0]), "+f"(c[1]), "+f"(c[2]), "+f"(c[3])
        : "r"(a[0]), "r"(a[1]), "r"(a[2]), "r"(a[3]), "r"(b[0]), "r"(b[1]));
}
__device__ __forceinline__ __half2 u2h(uint32_t u) { return *reinterpret_cast<__half2*>(&u); }

// ---------------- row map ----------------
__device__ __forceinline__ int win_row_to_orig(int r) {
    int bn = r / NTOK_, n = r - bn * NTOK_;
    int b  = bn >> 6,  wi = bn & 63;
    int i = n / WS_, j = n - i * WS_;
    int h = (wi >> 3) * WS_ + i + SHIFT_; if (h >= HW_) h -= HW_;
    int w = (wi & 7)  * WS_ + j + SHIFT_; if (w >= HW_) w -= HW_;
    return b * L_ + h * HW_ + w;
}

// ---------------- LayerNorm (half output) ----------------
template<bool SHIFT_WINDOW>
__global__ __launch_bounds__(128) void ln_kernel(const float* __restrict__ x,
                                                 const float* __restrict__ g,
                                                 const float* __restrict__ b,
                                                 __half* __restrict__ out)
{
    int r = blockIdx.x;
    int src_row = SHIFT_WINDOW ? win_row_to_orig(r) : r;
    const float* src = x + (size_t)src_row * C_;
    int t = threadIdx.x;
    float v[3], s = 0.f, s2 = 0.f;
#pragma unroll
    for (int l = 0; l < 3; ++l) { v[l] = src[t + l * 128]; s += v[l]; s2 += v[l] * v[l]; }
    __shared__ float red[8];
#pragma unroll
    for (int o = 16; o > 0; o >>= 1) {
        s  += __shfl_down_sync(0xffffffffu, s,  o);
        s2 += __shfl_down_sync(0xffffffffu, s2, o);
    }
    int lane = t & 31, wid = t >> 5;
    if (lane == 0) { red[wid] = s; red[4 + wid] = s2; }
    __syncthreads();
    s  = red[0] + red[1] + red[2] + red[3];
    s2 = red[4] + red[5] + red[6] + red[7];
    float mean = s * (1.f / C_);
    float var  = s2 * (1.f / C_) - mean * mean;
    float inv  = rsqrtf(var + 1e-5f);
    __half* dst = out + (size_t)r * C_;
#pragma unroll
    for (int l = 0; l < 3; ++l) {
        int c = t + l * 128;
        dst[c] = __float2half((v[l] - mean) * inv * g[c] + b[c]);
    }
}

// ---------------- weight transpose+convert ----------------
__global__ __launch_bounds__(256) void transpose_half(const float* __restrict__ src,
                                                      __half* __restrict__ dst,
                                                      int K, int N)
{
    __shared__ float t[32][33];
    int bx = blockIdx.x * 32, by = blockIdx.y * 32;
    int tx = threadIdx.x & 31, ty = threadIdx.x >> 5;
#pragma unroll
    for (int i = 0; i < 4; ++i)
        t[ty + i * 8][tx] = src[(size_t)(by + ty + i * 8) * N + bx + tx];
    __syncthreads();
#pragma unroll
    for (int i = 0; i < 4; ++i)
        dst[(size_t)(bx + ty + i * 8) * K + by + tx] = __float2half(t[tx][ty + i * 8]);
}

// ---------------- hybrid GEMM: tensor warps (cols 0-79) + HFMA2 warps (cols 80-127) --------
#define ASTR 40
#define ABYT (128 * ASTR * 2)
#define STGB (2 * ABYT)
#define NSTG 4
#define MM_SMEM (NSTG * STGB)

template<int EPI>
__global__ __launch_bounds__(512) void mm_kernel(const __half* __restrict__ A,
                                                 const __half* __restrict__ Wt,
                                                 const float* __restrict__ bias,
                                                 const float* __restrict__ Res,
                                                 void* __restrict__ OutV,
                                                 int K, int N)
{
    extern __shared__ __half sm[];
    const int tid = threadIdx.x;
    const int w = tid >> 5, lane = tid & 31;
    const bool is_t = (w < 8);
    // tensor warp ids
    const int warpM = w >> 1, warpN = w & 1;
    const int g = lane >> 2, tig = lane & 3;
    // fma warp ids
    const int f = w - 8;
    const int lr = lane >> 2, lc = lane & 3;
    const int r0f = f * 16 + lr, r1f = r0f + 8;

    const int bx = blockIdx.x, by = blockIdx.y;
    const __half* Ab = A  + (size_t)by * 128 * K;
    const __half* Bb = Wt + (size_t)bx * 128 * K;
    uint32_t s0 = (uint32_t)__cvta_generic_to_shared(sm);

    float accT[2][5][4];
    float accF[2][12];
    if (is_t) {
#pragma unroll
        for (int mt = 0; mt < 2; ++mt)
#pragma unroll
            for (int nt = 0; nt < 5; ++nt)
#pragma unroll
                for (int i = 0; i < 4; ++i) accT[mt][nt][i] = 0.f;
    } else {
#pragma unroll
        for (int j = 0; j < 2; ++j)
#pragma unroll
            for (int cc = 0; cc < 12; ++cc) accF[j][cc] = 0.f;
    }

    const int KT = K >> 5;

#define LOAD_STAGE(kt, st) do {                                                     \
        int _k0 = (kt) << 5;                                                        \
        uint32_t _ab = s0 + (st) * STGB;                                            \
        uint32_t _bb = _ab + ABYT;                                                  \
        int _r = tid >> 2, _sg = tid & 3;                                           \
        cp_async16(_ab + (_r * ASTR + _sg * 8) * 2, Ab + (size_t)_r * K + _k0 + _sg * 8); \
        cp_async16(_bb + (_r * ASTR + _sg * 8) * 2, Bb + (size_t)_r * K + _k0 + _sg * 8); \
        CP_COMMIT();                                                                \
    } while (0)

    LOAD_STAGE(0, 0);
    LOAD_STAGE(1, 1);

    const __half2 hz = __float2half2_rn(0.f);

    for (int kt = 0; kt < KT; ++kt) {
        int st = kt & 3;
        if (kt + 2 < KT)      { LOAD_STAGE(kt + 2, (kt + 2) & 3); CP_WAIT(2); }
        else if (kt + 1 < KT) { CP_WAIT(1); }
        else                  { CP_WAIT(0); }
        __syncthreads();

        if (is_t) {
            const uint32_t* Au = (const uint32_t*)(sm + st * (STGB / 2));
            const uint32_t* Bu = Au + ABYT / 4;
#pragma unroll
            for (int s = 0; s < 2; ++s) {
                uint32_t af[2][4], bf[5][2];
                int c2 = s * 8 + tig;
#pragma unroll
                for (int mt = 0; mt < 2; ++mt) {
                    int r = warpM * 32 + mt * 16 + g;
                    af[mt][0] = Au[r * 20 + c2];
                    af[mt][1] = Au[(r + 8) * 20 + c2];
                    af[mt][2] = Au[r * 20 + c2 + 4];
                    af[mt][3] = Au[(r + 8) * 20 + c2 + 4];
                }
#pragma unroll
                for (int nt = 0; nt < 5; ++nt) {
                    int n = warpN * 40 + nt * 8 + g;
                    bf[nt][0] = Bu[n * 20 + c2];
                    bf[nt][1] = Bu[n * 20 + c2 + 4];
                }
#pragma unroll
                for (int mt = 0; mt < 2; ++mt)
#pragma unroll
                    for (int nt = 0; nt < 5; ++nt)
                        mma16816(accT[mt][nt], af[mt], bf[nt]);
            }
        } else {
            const uint2* Au2 = (const uint2*)(sm + st * (STGB / 2));
            const uint2* Bu2 = Au2 + ABYT / 8;
#pragma unroll
            for (int hh = 0; hh < 2; ++hh) {          // two 16-k halves
                __half2 hacc[2][12];
#pragma unroll
                for (int j = 0; j < 2; ++j)
#pragma unroll
                    for (int cc = 0; cc < 12; ++cc) hacc[j][cc] = hz;
#pragma unroll
                for (int k4 = 0; k4 < 4; ++k4) {      // 4 k per iter
                    int o = hh * 4 + k4;              // uint2 k-offset
                    uint2 a0 = Au2[r0f * 10 + o];
                    uint2 a1 = Au2[r1f * 10 + o];
#pragma unroll
                    for (int cc = 0; cc < 12; ++cc) {
                        int n = 80 + cc * 4 + lc;
                        uint2 bb = Bu2[n * 10 + o];
                        hacc[0][cc] = __hfma2(u2h(a0.x), u2h(bb.x), hacc[0][cc]);
                        hacc[0][cc] = __hfma2(u2h(a0.y), u2h(bb.y), hacc[0][cc]);
                        hacc[1][cc] = __hfma2(u2h(a1.x), u2h(bb.x), hacc[1][cc]);
                        hacc[1][cc] = __hfma2(u2h(a1.y), u2h(bb.y), hacc[1][cc]);
                    }
                }
#pragma unroll
                for (int j = 0; j < 2; ++j)
#pragma unroll
                    for (int cc = 0; cc < 12; ++cc) {
                        float2 fp = __half22float2(hacc[j][cc]);
                        accF[j][cc] += fp.x + fp.y;
                    }
            }
        }
    }

    // ---------------- epilogue ----------------
    if (is_t) {
#pragma unroll
        for (int mt = 0; mt < 2; ++mt) {
#pragma unroll
            for (int rr = 0; rr < 2; ++rr) {
                int row = by * 128 + warpM * 32 + mt * 16 + g + rr * 8;
                if (EPI == 2) {
                    int orow = win_row_to_orig(row);
                    float* dst = (float*)OutV + (size_t)orow * C_;
                    const float* rs = Res + (size_t)orow * C_;
#pragma unroll
                    for (int nt = 0; nt < 5; ++nt) {
                        int c = bx * 128 + warpN * 40 + nt * 8 + tig * 2;
                        dst[c]     = accT[mt][nt][rr * 2]     + bias[c]     + rs[c];
                        dst[c + 1] = accT[mt][nt][rr * 2 + 1] + bias[c + 1] + rs[c + 1];
                    }
                } else if (EPI == 1) {
                    __half* dst = (__half*)OutV + (size_t)row * N;
#pragma unroll
                    for (int nt = 0; nt < 5; ++nt) {
                        int c = bx * 128 + warpN * 40 + nt * 8 + tig * 2;
                        float v0 = accT[mt][nt][rr * 2]     + bias[c];
                        float v1 = accT[mt][nt][rr * 2 + 1] + bias[c + 1];
                        v0 = 0.5f * v0 * (1.f + erff(v0 * 0.70710678118654752f));
                        v1 = 0.5f * v1 * (1.f + erff(v1 * 0.70710678118654752f));
                        *(__half2*)(dst + c) = __halves2half2(__float2half(v0), __float2half(v1));
                    }
                } else {
                    float* dst = (float*)OutV + (size_t)row * N;
#pragma unroll
                    for (int nt = 0; nt < 5; ++nt) {
                        int c = bx * 128 + warpN * 40 + nt * 8 + tig * 2;
                        float v0 = accT[mt][nt][rr * 2]     + bias[c];
                        float v1 = accT[mt][nt][rr * 2 + 1] + bias[c + 1];
                        if (EPI == 3) {
                            v0 += Res[(size_t)row * N + c];
                            v1 += Res[(size_t)row * N + c + 1];
                        }
                        dst[c] = v0; dst[c + 1] = v1;
                    }
                }
            }
        }
    } else {
        int rows[2] = { by * 128 + r0f, by * 128 + r1f };
#pragma unroll
        for (int j = 0; j < 2; ++j) {
            int row = rows[j];
            if (EPI == 2) {
                int orow = win_row_to_orig(row);
                float* dst = (float*)OutV + (size_t)orow * C_;
                const float* rs = Res + (size_t)orow * C_;
#pragma unroll
                for (int cc = 0; cc < 12; ++cc) {
                    int c = bx * 128 + 80 + cc * 4 + lc;
                    dst[c] = accF[j][cc] + bias[c] + rs[c];
                }
            } else if (EPI == 1) {
                __half* dst = (__half*)OutV + (size_t)row * N;
#pragma unroll
                for (int cc = 0; cc < 12; ++cc) {
                    int c = bx * 128 + 80 + cc * 4 + lc;
                    float v = accF[j][cc] + bias[c];
                    v = 0.5f * v * (1.f + erff(v * 0.70710678118654752f));
                    dst[c] = __float2half(v);
                }
            } else {
                float* dst = (float*)OutV + (size_t)row * N;
#pragma unroll
                for (int cc = 0; cc < 12; ++cc) {
                    int c = bx * 128 + 80 + cc * 4 + lc;
                    float v = accF[j][cc] + bias[c];
                    if (EPI == 3) v += Res[(size_t)row * N + c];
                    dst[c] = v;
                }
            }
        }
    }
}

// ---------------- Attention (half output) ----------------
__global__ __launch_bounds__(128) void attn_kernel(const float* __restrict__ rpb,
                                                   const float* __restrict__ mask)
{
    int bh = blockIdx.x;
    int bn = bh / NH_, head = bh - bn * NH_;
    int t = threadIdx.x;

    __shared__ float q [NTOK_][HD_];
    __shared__ float kk[NTOK_][HD_];
    __shared__ float vv[NTOK_][HD_];
    __shared__ float s [NTOK_][52];

    const float* base = g_qkv + (size_t)bn * NTOK_ * QKVN_ + head * HD_;
    for (int idx = t; idx < NTOK_ * HD_; idx += 128) {
        int n = idx >> 5, d = idx & 31;
        const float* p = base + (size_t)n * QKVN_ + d;
        q [n][d] = p[0]   * SCALE_;
        kk[n][d] = p[C_];
        vv[n][d] = p[2 * C_];
    }
    __syncthreads();

    int wi = bn & 63;
    const float* mrow = mask + (size_t)wi * NTOK_ * NTOK_;
    for (int idx = t; idx < NTOK_ * NTOK_; idx += 128) {
        int n = idx / NTOK_, m = idx - n * NTOK_;
        float acc = 0.f;
#pragma unroll
        for (int d = 0; d < HD_; ++d) acc = fmaf(q[n][d], kk[m][d], acc);
        int di = n / WS_ - m / WS_ + WS_ - 1;
        int dj = n % WS_ - m % WS_ + WS_ - 1;
        acc += rpb[(di * (2 * WS_ - 1) + dj) * NH_ + head] + mrow[idx];
        s[n][m] = acc;
    }
    __syncthreads();

    if (t < NTOK_) {
        float mx = -1e30f;
#pragma unroll 7
        for (int m = 0; m < NTOK_; ++m) mx = fmaxf(mx, s[t][m]);
        float sum = 0.f;
#pragma unroll 7
        for (int m = 0; m < NTOK_; ++m) { float e = __expf(s[t][m] - mx); s[t][m] = e; sum += e; }
        float inv = 1.f / sum;
#pragma unroll 7
        for (int m = 0; m < NTOK_; ++m) s[t][m] *= inv;
    }
    __syncthreads();

    for (int idx = t; idx < NTOK_ * HD_; idx += 128) {
        int n = idx >> 5, d = idx & 31;
        float acc = 0.f;
#pragma unroll 7
        for (int m = 0; m < NTOK_; ++m) acc = fmaf(s[n][m], vv[m][d], acc);
        g_att[((size_t)bn * NTOK_ + n) * C_ + head * HD_ + d] = __float2half(acc);
    }
}

// ---------------- launch ----------------
extern "C" void kernel_launch(void* const* d_in, const int* in_sizes, int n_in,
                              void* d_out, int out_size)
{
    const float* x       = (const float*)d_in[0];
    const float* mask    = (const float*)d_in[1];
    const float* n1g     = (const float*)d_in[2];
    const float* n1b     = (const float*)d_in[3];
    const float* qkv_w   = (const float*)d_in[4];
    const float* qkv_b   = (const float*)d_in[5];
    const float* rpb     = (const float*)d_in[6];
    const float* proj_w  = (const float*)d_in[7];
    const float* proj_b  = (const float*)d_in[8];
    const float* n2g     = (const float*)d_in[9];
    const float* n2b     = (const float*)d_in[10];
    const float* fc1_w   = (const float*)d_in[11];
    const float* fc1_b   = (const float*)d_in[12];
    const float* fc2_w   = (const float*)d_in[13];
    const float* fc2_b   = (const float*)d_in[14];
    float* out = (float*)d_out;

    __half *p_win, *p_att, *p_h2, *p_hid;
    float  *p_qkv, *p_x1;
    __half *pW_qkv, *pW_proj, *pW_fc1, *pW_fc2;
    cudaGetSymbolAddress((void**)&p_win, g_win);
    cudaGetSymbolAddress((void**)&p_qkv, g_qkv);
    cudaGetSymbolAddress((void**)&p_att, g_att);
    cudaGetSymbolAddress((void**)&p_x1,  g_x1);
    cudaGetSymbolAddress((void**)&p_h2,  g_h2);
    cudaGetSymbolAddress((void**)&p_hid, g_hid);
    cudaGetSymbolAddress((void**)&pW_qkv,  g_wh_qkv);
    cudaGetSymbolAddress((void**)&pW_proj, g_wh_proj);
    cudaGetSymbolAddress((void**)&pW_fc1,  g_wh_fc1);
    cudaGetSymbolAddress((void**)&pW_fc2,  g_wh_fc2);

    cudaFuncSetAttribute(mm_kernel<0>, cudaFuncAttributeMaxDynamicSharedMemorySize, MM_SMEM);
    cudaFuncSetAttribute(mm_kernel<1>, cudaFuncAttributeMaxDynamicSharedMemorySize, MM_SMEM);
    cudaFuncSetAttribute(mm_kernel<2>, cudaFuncAttributeMaxDynamicSharedMemorySize, MM_SMEM);
    cudaFuncSetAttribute(mm_kernel<3>, cudaFuncAttributeMaxDynamicSharedMemorySize, MM_SMEM);

    // 0) transpose + fp16-convert weights -> [N,K]
    transpose_half<<<dim3(QKVN_ / 32, C_ / 32), 256>>>(qkv_w, pW_qkv, C_, QKVN_);
    transpose_half<<<dim3(C_ / 32, C_ / 32), 256>>>(proj_w, pW_proj, C_, C_);
    transpose_half<<<dim3(HID_ / 32, C_ / 32), 256>>>(fc1_w, pW_fc1, C_, HID_);
    transpose_half<<<dim3(C_ / 32, HID_ / 32), 256>>>(fc2_w, pW_fc2, HID_, C_);

    // 1) LN1 + roll + window partition (half)
    ln_kernel<true><<<MTOT_, 128>>>(x, n1g, n1b, p_win);

    // 2) QKV GEMM -> float
    mm_kernel<0><<<dim3(QKVN_ / 128, MTOT_ / 128), 512, MM_SMEM>>>(p_win, pW_qkv, qkv_b, nullptr,
                                                                   p_qkv, C_, QKVN_);
    // 3) windowed attention -> half
    attn_kernel<<<BN_ * NH_, 128>>>(rpb, mask);

    // 4) proj + window reverse + residual -> float (orig order)
    mm_kernel<2><<<dim3(C_ / 128, MTOT_ / 128), 512, MM_SMEM>>>(p_att, pW_proj, proj_b, x,
                                                                p_x1, C_, C_);
    // 5) LN2 -> half
    ln_kernel<false><<<MTOT_, 128>>>(p_x1, n2g, n2b, p_h2);

    // 6) fc1 + GELU -> half
    mm_kernel<1><<<dim3(HID_ / 128, MTOT_ / 128), 512, MM_SMEM>>>(p_h2, pW_fc1, fc1_b, nullptr,
                                                                  p_hid, C_, HID_);
    // 7) fc2 + residual -> out (float)
    mm_kernel<3><<<dim3(C_ / 128, MTOT_ / 128), 512, MM_SMEM>>>(p_hid, pW_fc2, fc2_b, p_x1,
                                                                out, HID_, C_);
}

// round 9
// speedup vs baseline: 1.8242x; 1.8242x over previous
#include <cuda_runtime.h>
#include <cuda_fp16.h>
#include <math.h>
#include <stdint.h>

// ---------------- problem constants ----------------
#define B_      32
#define HW_     56
#define L_      3136
#define C_      384
#define NH_     12
#define HD_     32
#define WS_     7
#define NTOK_   49
#define NWIN_   64
#define BN_     2048
#define MTOT_   100352
#define HID_    1536
#define QKVN_   1152
#define SHIFT_  3
#define SCALE_  0.17677669529663687f

// ---------------- scratch ----------------
__device__ __half g_win[(size_t)MTOT_ * C_];
__device__ __half g_qkv[(size_t)MTOT_ * QKVN_];   // now half
__device__ __half g_att[(size_t)MTOT_ * C_];
__device__ float  g_x1 [(size_t)MTOT_ * C_];
__device__ __half g_h2 [(size_t)MTOT_ * C_];
__device__ __half g_hid[(size_t)MTOT_ * HID_];
__device__ __half g_wh_qkv[(size_t)QKVN_ * C_];
__device__ __half g_wh_proj[(size_t)C_ * C_];
__device__ __half g_wh_fc1[(size_t)HID_ * C_];
__device__ __half g_wh_fc2[(size_t)C_ * HID_];

// ---------------- helpers ----------------
__device__ __forceinline__ void cp_async16(uint32_t saddr, const void* gptr) {
    asm volatile("cp.async.cg.shared.global [%0], [%1], 16;" :: "r"(saddr), "l"(gptr));
}
#define CP_COMMIT() asm volatile("cp.async.commit_group;" ::: "memory")
#define CP_WAIT(n)  asm volatile("cp.async.wait_group %0;" :: "n"(n) : "memory")

__device__ __forceinline__ void mma16816(float* c, const uint32_t* a, const uint32_t* b) {
    asm volatile("mma.sync.aligned.m16n8k16.row.col.f32.f16.f16.f32 "
        "{%0,%1,%2,%3}, {%4,%5,%6,%7}, {%8,%9}, {%0,%1,%2,%3};"
        : "+f"(c[0]), "+f"(c[1]), "+f"(c[2]), "+f"(c[3])
        : "r"(a[0]), "r"(a[1]), "r"(a[2]), "r"(a[3]), "r"(b[0]), "r"(b[1]));
}

// ---------------- row map ----------------
__device__ __forceinline__ int win_row_to_orig(int r) {
    int bn = r / NTOK_, n = r - bn * NTOK_;
    int b  = bn >> 6,  wi = bn & 63;
    int i = n / WS_, j = n - i * WS_;
    int h = (wi >> 3) * WS_ + i + SHIFT_; if (h >= HW_) h -= HW_;
    int w = (wi & 7)  * WS_ + j + SHIFT_; if (w >= HW_) w -= HW_;
    return b * L_ + h * HW_ + w;
}

// ---------------- LayerNorm (half output) ----------------
template<bool SHIFT_WINDOW>
__global__ __launch_bounds__(128) void ln_kernel(const float* __restrict__ x,
                                                 const float* __restrict__ g,
                                                 const float* __restrict__ b,
                                                 __half* __restrict__ out)
{
    int r = blockIdx.x;
    int src_row = SHIFT_WINDOW ? win_row_to_orig(r) : r;
    const float* src = x + (size_t)src_row * C_;
    int t = threadIdx.x;
    float v[3], s = 0.f, s2 = 0.f;
#pragma unroll
    for (int l = 0; l < 3; ++l) { v[l] = src[t + l * 128]; s += v[l]; s2 += v[l] * v[l]; }
    __shared__ float red[8];
#pragma unroll
    for (int o = 16; o > 0; o >>= 1) {
        s  += __shfl_down_sync(0xffffffffu, s,  o);
        s2 += __shfl_down_sync(0xffffffffu, s2, o);
    }
    int lane = t & 31, wid = t >> 5;
    if (lane == 0) { red[wid] = s; red[4 + wid] = s2; }
    __syncthreads();
    s  = red[0] + red[1] + red[2] + red[3];
    s2 = red[4] + red[5] + red[6] + red[7];
    float mean = s * (1.f / C_);
    float var  = s2 * (1.f / C_) - mean * mean;
    float inv  = rsqrtf(var + 1e-5f);
    __half* dst = out + (size_t)r * C_;
#pragma unroll
    for (int l = 0; l < 3; ++l) {
        int c = t + l * 128;
        dst[c] = __float2half((v[l] - mean) * inv * g[c] + b[c]);
    }
}

// ---------------- weight transpose+convert ----------------
__global__ __launch_bounds__(256) void transpose_half(const float* __restrict__ src,
                                                      __half* __restrict__ dst,
                                                      int K, int N)
{
    __shared__ float t[32][33];
    int bx = blockIdx.x * 32, by = blockIdx.y * 32;
    int tx = threadIdx.x & 31, ty = threadIdx.x >> 5;
#pragma unroll
    for (int i = 0; i < 4; ++i)
        t[ty + i * 8][tx] = src[(size_t)(by + ty + i * 8) * N + bx + tx];
    __syncthreads();
#pragma unroll
    for (int i = 0; i < 4; ++i)
        dst[(size_t)(bx + ty + i * 8) * K + by + tx] = __float2half(t[tx][ty + i * 8]);
}

// ---------------- fp16 mma GEMM: 128x128 block, 8 warps, 4-stage 1-sync ring ----------------
// EPI: 0=+bias->half ; 1=+bias,gelu->half ; 2=+bias,win-rev+residual->float ;
//      3=+bias+residual->float
#define ASTR 40
#define ABYT (128 * ASTR * 2)
#define STGB (2 * ABYT)
#define NSTG 4
#define MM_SMEM (NSTG * STGB)

template<int EPI>
__global__ __launch_bounds__(256, 2) void mm_kernel(const __half* __restrict__ A,
                                                    const __half* __restrict__ Wt,
                                                    const float* __restrict__ bias,
                                                    const float* __restrict__ Res,
                                                    void* __restrict__ OutV,
                                                    int K, int N)
{
    extern __shared__ __half sm[];
    const int tid = threadIdx.x;
    const int w = tid >> 5, lane = tid & 31;
    const int warpM = w >> 1, warpN = w & 1;
    const int g = lane >> 2, tig = lane & 3;
    const int bx = blockIdx.x, by = blockIdx.y;

    const __half* Ab = A  + (size_t)by * 128 * K;
    const __half* Bb = Wt + (size_t)bx * 128 * K;
    uint32_t s0 = (uint32_t)__cvta_generic_to_shared(sm);

    float acc[2][8][4];
#pragma unroll
    for (int mt = 0; mt < 2; ++mt)
#pragma unroll
        for (int nt = 0; nt < 8; ++nt)
#pragma unroll
            for (int i = 0; i < 4; ++i) acc[mt][nt][i] = 0.f;

    const int KT = K >> 5;
    const int ca0 = tid, ca1 = tid + 256;

#define LOAD_STAGE(kt, st) do {                                                     \
        int _k0 = (kt) << 5;                                                        \
        uint32_t _ab = s0 + (st) * STGB;                                            \
        uint32_t _bb = _ab + ABYT;                                                  \
        { int r = ca0 >> 2, sg = ca0 & 3;                                           \
          cp_async16(_ab + (r * ASTR + sg * 8) * 2, Ab + (size_t)r * K + _k0 + sg * 8); } \
        { int r = ca1 >> 2, sg = ca1 & 3;                                           \
          cp_async16(_ab + (r * ASTR + sg * 8) * 2, Ab + (size_t)r * K + _k0 + sg * 8); } \
        { int r = ca0 >> 2, sg = ca0 & 3;                                           \
          cp_async16(_bb + (r * ASTR + sg * 8) * 2, Bb + (size_t)r * K + _k0 + sg * 8); } \
        { int r = ca1 >> 2, sg = ca1 & 3;                                           \
          cp_async16(_bb + (r * ASTR + sg * 8) * 2, Bb + (size_t)r * K + _k0 + sg * 8); } \
        CP_COMMIT();                                                                \
    } while (0)

    LOAD_STAGE(0, 0);
    LOAD_STAGE(1, 1);

    for (int kt = 0; kt < KT; ++kt) {
        int st = kt & 3;
        if (kt + 2 < KT)      { LOAD_STAGE(kt + 2, (kt + 2) & 3); CP_WAIT(2); }
        else if (kt + 1 < KT) { CP_WAIT(1); }
        else                  { CP_WAIT(0); }
        __syncthreads();

        const uint32_t* Au = (const uint32_t*)(sm + st * (STGB / 2));
        const uint32_t* Bu = Au + ABYT / 4;
#pragma unroll
        for (int s = 0; s < 2; ++s) {
            uint32_t af[2][4], bf[8][2];
            int c2 = s * 8 + tig;
#pragma unroll
            for (int mt = 0; mt < 2; ++mt) {
                int r = warpM * 32 + mt * 16 + g;
                af[mt][0] = Au[r * 20 + c2];
                af[mt][1] = Au[(r + 8) * 20 + c2];
                af[mt][2] = Au[r * 20 + c2 + 4];
                af[mt][3] = Au[(r + 8) * 20 + c2 + 4];
            }
#pragma unroll
            for (int nt = 0; nt < 8; ++nt) {
                int n = warpN * 64 + nt * 8 + g;
                bf[nt][0] = Bu[n * 20 + c2];
                bf[nt][1] = Bu[n * 20 + c2 + 4];
            }
#pragma unroll
            for (int mt = 0; mt < 2; ++mt)
#pragma unroll
                for (int nt = 0; nt < 8; ++nt)
                    mma16816(acc[mt][nt], af[mt], bf[nt]);
        }
    }

    // ---------------- epilogue ----------------
#pragma unroll
    for (int mt = 0; mt < 2; ++mt) {
#pragma unroll
        for (int rr = 0; rr < 2; ++rr) {
            int row = by * 128 + warpM * 32 + mt * 16 + g + rr * 8;
            if (EPI == 2) {
                int orow = win_row_to_orig(row);
                float* dst = (float*)OutV + (size_t)orow * C_;
                const float* rs = Res + (size_t)orow * C_;
#pragma unroll
                for (int nt = 0; nt < 8; ++nt) {
                    int c = bx * 128 + warpN * 64 + nt * 8 + tig * 2;
                    dst[c]     = acc[mt][nt][rr * 2]     + bias[c]     + rs[c];
                    dst[c + 1] = acc[mt][nt][rr * 2 + 1] + bias[c + 1] + rs[c + 1];
                }
            } else if (EPI == 0 || EPI == 1) {
                __half* dst = (__half*)OutV + (size_t)row * N;
#pragma unroll
                for (int nt = 0; nt < 8; ++nt) {
                    int c = bx * 128 + warpN * 64 + nt * 8 + tig * 2;
                    float v0 = acc[mt][nt][rr * 2]     + bias[c];
                    float v1 = acc[mt][nt][rr * 2 + 1] + bias[c + 1];
                    if (EPI == 1) {
                        v0 = 0.5f * v0 * (1.f + erff(v0 * 0.70710678118654752f));
                        v1 = 0.5f * v1 * (1.f + erff(v1 * 0.70710678118654752f));
                    }
                    *(__half2*)(dst + c) = __halves2half2(__float2half(v0), __float2half(v1));
                }
            } else {
                float* dst = (float*)OutV + (size_t)row * N;
#pragma unroll
                for (int nt = 0; nt < 8; ++nt) {
                    int c = bx * 128 + warpN * 64 + nt * 8 + tig * 2;
                    float v0 = acc[mt][nt][rr * 2]     + bias[c];
                    float v1 = acc[mt][nt][rr * 2 + 1] + bias[c + 1];
                    v0 += Res[(size_t)row * N + c];
                    v1 += Res[(size_t)row * N + c + 1];
                    dst[c] = v0; dst[c + 1] = v1;
                }
            }
        }
    }
}

// ---------------- Attention (half qkv in, half out) ----------------
__global__ __launch_bounds__(128) void attn_kernel(const float* __restrict__ rpb,
                                                   const float* __restrict__ mask)
{
    int bh = blockIdx.x;
    int bn = bh / NH_, head = bh - bn * NH_;
    int t = threadIdx.x;

    __shared__ float q [NTOK_][HD_];
    __shared__ float kk[NTOK_][HD_];
    __shared__ float vv[NTOK_][HD_];
    __shared__ float s [NTOK_][52];

    const __half* base = g_qkv + (size_t)bn * NTOK_ * QKVN_ + head * HD_;
    for (int idx = t; idx < NTOK_ * HD_; idx += 128) {
        int n = idx >> 5, d = idx & 31;
        const __half* p = base + (size_t)n * QKVN_ + d;
        q [n][d] = __half2float(p[0]) * SCALE_;
        kk[n][d] = __half2float(p[C_]);
        vv[n][d] = __half2float(p[2 * C_]);
    }
    __syncthreads();

    int wi = bn & 63;
    const float* mrow = mask + (size_t)wi * NTOK_ * NTOK_;
    for (int idx = t; idx < NTOK_ * NTOK_; idx += 128) {
        int n = idx / NTOK_, m = idx - n * NTOK_;
        float acc = 0.f;
#pragma unroll
        for (int d = 0; d < HD_; ++d) acc = fmaf(q[n][d], kk[m][d], acc);
        int di = n / WS_ - m / WS_ + WS_ - 1;
        int dj = n % WS_ - m % WS_ + WS_ - 1;
        acc += rpb[(di * (2 * WS_ - 1) + dj) * NH_ + head] + mrow[idx];
        s[n][m] = acc;
    }
    __syncthreads();

    if (t < NTOK_) {
        float mx = -1e30f;
#pragma unroll 7
        for (int m = 0; m < NTOK_; ++m) mx = fmaxf(mx, s[t][m]);
        float sum = 0.f;
#pragma unroll 7
        for (int m = 0; m < NTOK_; ++m) { float e = __expf(s[t][m] - mx); s[t][m] = e; sum += e; }
        float inv = 1.f / sum;
#pragma unroll 7
        for (int m = 0; m < NTOK_; ++m) s[t][m] *= inv;
    }
    __syncthreads();

    for (int idx = t; idx < NTOK_ * HD_; idx += 128) {
        int n = idx >> 5, d = idx & 31;
        float acc = 0.f;
#pragma unroll 7
        for (int m = 0; m < NTOK_; ++m) acc = fmaf(s[n][m], vv[m][d], acc);
        g_att[((size_t)bn * NTOK_ + n) * C_ + head * HD_ + d] = __float2half(acc);
    }
}

// ---------------- launch ----------------
extern "C" void kernel_launch(void* const* d_in, const int* in_sizes, int n_in,
                              void* d_out, int out_size)
{
    const float* x       = (const float*)d_in[0];
    const float* mask    = (const float*)d_in[1];
    const float* n1g     = (const float*)d_in[2];
    const float* n1b     = (const float*)d_in[3];
    const float* qkv_w   = (const float*)d_in[4];
    const float* qkv_b   = (const float*)d_in[5];
    const float* rpb     = (const float*)d_in[6];
    const float* proj_w  = (const float*)d_in[7];
    const float* proj_b  = (const float*)d_in[8];
    const float* n2g     = (const float*)d_in[9];
    const float* n2b     = (const float*)d_in[10];
    const float* fc1_w   = (const float*)d_in[11];
    const float* fc1_b   = (const float*)d_in[12];
    const float* fc2_w   = (const float*)d_in[13];
    const float* fc2_b   = (const float*)d_in[14];
    float* out = (float*)d_out;

    __half *p_win, *p_qkv, *p_att, *p_h2, *p_hid;
    float  *p_x1;
    __half *pW_qkv, *pW_proj, *pW_fc1, *pW_fc2;
    cudaGetSymbolAddress((void**)&p_win, g_win);
    cudaGetSymbolAddress((void**)&p_qkv, g_qkv);
    cudaGetSymbolAddress((void**)&p_att, g_att);
    cudaGetSymbolAddress((void**)&p_x1,  g_x1);
    cudaGetSymbolAddress((void**)&p_h2,  g_h2);
    cudaGetSymbolAddress((void**)&p_hid, g_hid);
    cudaGetSymbolAddress((void**)&pW_qkv,  g_wh_qkv);
    cudaGetSymbolAddress((void**)&pW_proj, g_wh_proj);
    cudaGetSymbolAddress((void**)&pW_fc1,  g_wh_fc1);
    cudaGetSymbolAddress((void**)&pW_fc2,  g_wh_fc2);

    cudaFuncSetAttribute(mm_kernel<0>, cudaFuncAttributeMaxDynamicSharedMemorySize, MM_SMEM);
    cudaFuncSetAttribute(mm_kernel<1>, cudaFuncAttributeMaxDynamicSharedMemorySize, MM_SMEM);
    cudaFuncSetAttribute(mm_kernel<2>, cudaFuncAttributeMaxDynamicSharedMemorySize, MM_SMEM);
    cudaFuncSetAttribute(mm_kernel<3>, cudaFuncAttributeMaxDynamicSharedMemorySize, MM_SMEM);

    // 0) transpose + fp16-convert weights -> [N,K]
    transpose_half<<<dim3(QKVN_ / 32, C_ / 32), 256>>>(qkv_w, pW_qkv, C_, QKVN_);
    transpose_half<<<dim3(C_ / 32, C_ / 32), 256>>>(proj_w, pW_proj, C_, C_);
    transpose_half<<<dim3(HID_ / 32, C_ / 32), 256>>>(fc1_w, pW_fc1, C_, HID_);
    transpose_half<<<dim3(C_ / 32, HID_ / 32), 256>>>(fc2_w, pW_fc2, HID_, C_);

    // 1) LN1 + roll + window partition (half)
    ln_kernel<true><<<MTOT_, 128>>>(x, n1g, n1b, p_win);

    // 2) QKV GEMM -> half
    mm_kernel<0><<<dim3(QKVN_ / 128, MTOT_ / 128), 256, MM_SMEM>>>(p_win, pW_qkv, qkv_b, nullptr,
                                                                   p_qkv, C_, QKVN_);
    // 3) windowed attention -> half
    attn_kernel<<<BN_ * NH_, 128>>>(rpb, mask);

    // 4) proj + window reverse + residual -> float (orig order)
    mm_kernel<2><<<dim3(C_ / 128, MTOT_ / 128), 256, MM_SMEM>>>(p_att, pW_proj, proj_b, x,
                                                                p_x1, C_, C_);
    // 5) LN2 -> half
    ln_kernel<false><<<MTOT_, 128>>>(p_x1, n2g, n2b, p_h2);

    // 6) fc1 + GELU -> half
    mm_kernel<1><<<dim3(HID_ / 128, MTOT_ / 128), 256, MM_SMEM>>>(p_h2, pW_fc1, fc1_b, nullptr,
                                                                  p_hid, C_, HID_);
    // 7) fc2 + residual -> out (float)
    mm_kernel<3><<<dim3(C_ / 128, MTOT_ / 128), 256, MM_SMEM>>>(p_hid, pW_fc2, fc2_b, p_x1,
                                                                out, HID_, C_);
}